// round 13
// baseline (speedup 1.0000x reference)
#include <cuda_runtime.h>
#include <cuda_fp16.h>
#include <cstdint>
#include <limits.h>

// ---------------- problem constants ----------------
#define BATCH   8
#define CDIM    64
#define GDIM    65536
#define NLAYER  4
#define SLOPE   0.1f

#define TPB     256
#define CTAS_PER_SM 2
#define GRID    (148 * CTAS_PER_SM)         // 296
#define WARPS_PER_CTA (TPB / 32)
#define NWARPS  (GRID * WARPS_PER_CTA)      // 2368
#define WARPS_PER_BATCH (NWARPS / BATCH)    // 296
#define TILES_PER_BATCH (GDIM / 32)         // 2048 tiles of 32 columns

// smem layout (dynamic)
#define SMB_BYTES   (4 * 4 * 4 * 32 * 16)   // B fragment pairs: 32768
#define SMBIAS_OFF  SMB_BYTES               // 8 x 4 x 64 fp32 = 8192
#define SMX0_OFF    (SMBIAS_OFF + 8192)     // 512 fp32
#define SMY_OFF     (SMX0_OFF + 2048)       // 512 fp32
#define SM_TOTAL    (SMY_OFF + 2048)        // 45056

#define NEG_INF __int_as_float(0xff800000)

// ---------------- helpers ----------------
__device__ __forceinline__ uint32_t pack_h2(float a, float b) {
    uint32_t p;
    asm("cvt.rn.f16x2.f32 %0, %1, %2;" : "=r"(p) : "f"(b), "f"(a));
    return p;
}

#define MMA16816(d, a0, a1, a2, a3, b0, b1) \
    asm volatile("mma.sync.aligned.m16n8k16.row.col.f32.f16.f16.f32 " \
        "{%0,%1,%2,%3}, {%4,%5,%6,%7}, {%8,%9}, {%0,%1,%2,%3};" \
        : "+f"((d)[0]), "+f"((d)[1]), "+f"((d)[2]), "+f"((d)[3]) \
        : "r"(a0), "r"(a1), "r"(a2), "r"(a3), "r"(b0), "r"(b1))

// monotone uint key; 0 == -inf sentinel (matches zero-init of __device__ globals)
__device__ __forceinline__ unsigned f2ukey(float f) {
    int b = __float_as_int(f);
    b = (b >= 0) ? b : (b ^ 0x7fffffff);
    return (unsigned)b ^ 0x80000000u;
}
__device__ __forceinline__ float ukey2f(unsigned u) {
    int k = (int)(u ^ 0x80000000u);
    return __int_as_float(k >= 0 ? k : (k ^ 0x7fffffff));
}
__device__ __forceinline__ float lrelu(float a) { return fmaxf(a, SLOPE * a); }

// ---------------- device globals (zero-initialized .bss; kernel restores 0) --
__device__ unsigned g_maxkey[BATCH * 64];
__device__ int      g_done;

// ---------------- the single fused kernel -----------------------------------
__global__ void __launch_bounds__(TPB, CTAS_PER_SM)
mlp_kernel(const float* __restrict__ feat,
           const float* __restrict__ W0, const float* __restrict__ W1,
           const float* __restrict__ W2, const float* __restrict__ W3,
           float* __restrict__ out) {
    extern __shared__ char smem[];
    uint4* sB    = (uint4*)smem;                    // [l][sb:4][jp:4][lane:32]
    float* sbias = (float*)(smem + SMBIAS_OFF);     // [b][l][o]
    float* sx0   = (float*)(smem + SMX0_OFF);       // [b][c]
    float* sy0   = (float*)(smem + SMY_OFF);        // [b][o]

    const int tid  = threadIdx.x;
    const int wid  = tid >> 5;
    const int lane = tid & 31;
    const int g    = lane >> 2;
    const int t    = lane & 3;

    const float* Ws[NLAYER] = {W0, W1, W2, W3};

    // ---- prologue A: pack B fragment PAIRS (Weff -> fp16) + x0 load ----
    for (int idx = tid; idx < 4 * 4 * 4 * 32; idx += TPB) {
        int ln = idx & 31, jp = (idx >> 5) & 3, sb = (idx >> 7) & 3, l = idx >> 9;
        int gg = ln >> 2, tt = ln & 3;
        int cb = 16 * sb + 2 * tt;
        uint32_t v[4];
        #pragma unroll
        for (int h = 0; h < 2; h++) {
            int o = 8 * (2 * jp + h) + gg;
            const float* W = Ws[l] + o * 128;
            float v0 = W[cb]     + W[64 + cb];
            float v1 = W[cb + 1] + W[64 + cb + 1];
            float v8 = W[cb + 8] + W[64 + cb + 8];
            float v9 = W[cb + 9] + W[64 + cb + 9];
            v[2 * h]     = pack_h2(v0, v1);
            v[2 * h + 1] = pack_h2(v8, v9);
        }
        sB[idx] = make_uint4(v[0], v[1], v[2], v[3]);
    }
    for (int idx = tid; idx < BATCH * 64; idx += TPB) {
        int b = idx >> 6, c = idx & 63;
        sx0[idx] = __ldg(feat + (size_t)b * CDIM * GDIM + (size_t)c * GDIM); // g=0
    }
    __syncthreads();

    // ---- prologue B: bias chain (exact fp32, redundant per CTA, ~1.5us) ----
    #pragma unroll 1
    for (int l = 0; l < NLAYER; l++) {
        const float* W = Ws[l];
        for (int idx = tid; idx < BATCH * 64; idx += TPB) {
            int b = idx >> 6, o = idx & 63;
            const float* wr = W + o * 128;
            const float* xr = sx0 + b * 64;
            float da = 0.f, db = 0.f;
            #pragma unroll
            for (int c = 0; c < 64; c++) {
                float xv = xr[c];
                da = fmaf(wr[c], xv, da);
                db = fmaf(wr[64 + c], xv, db);
            }
            sbias[(b * 4 + l) * 64 + o] = -db;
            sy0[idx] = lrelu(da);
        }
        __syncthreads();
        if (l < NLAYER - 1) {
            for (int idx = tid; idx < BATCH * 64; idx += TPB) sx0[idx] = sy0[idx];
            __syncthreads();
        }
    }

    // ---- batch-locked warp -> tile mapping ----
    const int wglobal = blockIdx.x * WARPS_PER_CTA + wid;
    const int b       = wglobal & 7;
    const int tstart  = wglobal >> 3;
    const float* fbase = feat + (size_t)b * CDIM * GDIM;
    const float* sbias_b = sbias + b * NLAYER * 64;

    // register running max (this lane's D-rows only; cross-row reduce at end)
    float Rm0[8], Rm1[8];
    #pragma unroll
    for (int j = 0; j < 8; j++) { Rm0[j] = NEG_INF; Rm1[j] = NEG_INF; }

    for (int ti = tstart; ti < TILES_PER_BATCH; ti += WARPS_PER_BATCH) {
        // ---- vectorized X load (column-permuted fragment mapping) ----
        // fragment row r of half0 -> col 4r, row r+8 -> col 4r+1,
        // half1 rows -> cols 4r+2, 4r+3. Lane (g,t) loads float4 at col 4g.
        uint32_t A0[16], A1[16];
        {
            const float* fp = fbase + ((uint32_t)ti << 5);
            #pragma unroll
            for (int s = 0; s < 4; s++) {
                const uint32_t c0 = 16 * s + 2 * t;
                const float4 v0 = __ldg((const float4*)(fp + (size_t)c0 * GDIM) + g);
                const float4 v1 = __ldg((const float4*)(fp + (size_t)(c0 + 1) * GDIM) + g);
                const float4 v8 = __ldg((const float4*)(fp + (size_t)(c0 + 8) * GDIM) + g);
                const float4 v9 = __ldg((const float4*)(fp + (size_t)(c0 + 9) * GDIM) + g);
                A0[4*s+0] = pack_h2(v0.x, v1.x);
                A0[4*s+1] = pack_h2(v0.y, v1.y);
                A0[4*s+2] = pack_h2(v8.x, v9.x);
                A0[4*s+3] = pack_h2(v8.y, v9.y);
                A1[4*s+0] = pack_h2(v0.z, v1.z);
                A1[4*s+1] = pack_h2(v0.w, v1.w);
                A1[4*s+2] = pack_h2(v8.z, v9.z);
                A1[4*s+3] = pack_h2(v8.w, v9.w);
            }
        }

        // ---- layers 0..2: all-j-live D, in-place A rewrite ----
        #pragma unroll 1
        for (int l = 0; l < NLAYER - 1; l++) {
            float D0[8][4], D1[8][4];
            const float2* bp = (const float2*)(sbias_b + l * 64);
            #pragma unroll
            for (int j = 0; j < 8; j++) {
                float2 bv = bp[4 * j + t];
                D0[j][0] = bv.x; D0[j][1] = bv.y; D0[j][2] = bv.x; D0[j][3] = bv.y;
                D1[j][0] = bv.x; D1[j][1] = bv.y; D1[j][2] = bv.x; D1[j][3] = bv.y;
            }
            const uint4* Bl = sB + l * (4 * 4 * 32) + lane;
            #pragma unroll
            for (int sb = 0; sb < 4; sb++) {
                const uint32_t* p0 = A0 + 4 * sb;
                const uint32_t* p1 = A1 + 4 * sb;
                #pragma unroll
                for (int jp = 0; jp < 4; jp++) {
                    uint4 bf = Bl[(sb * 4 + jp) * 32];
                    MMA16816(D0[2*jp],   p0[0], p0[1], p0[2], p0[3], bf.x, bf.y);
                    MMA16816(D1[2*jp],   p1[0], p1[1], p1[2], p1[3], bf.x, bf.y);
                    MMA16816(D0[2*jp+1], p0[0], p0[1], p0[2], p0[3], bf.z, bf.w);
                    MMA16816(D1[2*jp+1], p1[0], p1[1], p1[2], p1[3], bf.z, bf.w);
                }
            }
            #pragma unroll
            for (int j = 0; j < 8; j++) {
                const int s4 = ((j >> 1) << 2) + ((j & 1) << 1);
                A0[s4 + 0] = pack_h2(lrelu(D0[j][0]), lrelu(D0[j][1]));
                A0[s4 + 1] = pack_h2(lrelu(D0[j][2]), lrelu(D0[j][3]));
                A1[s4 + 0] = pack_h2(lrelu(D1[j][0]), lrelu(D1[j][1]));
                A1[s4 + 1] = pack_h2(lrelu(D1[j][2]), lrelu(D1[j][3]));
            }
        }

        // ---- final layer: j-outer (8 D regs live), fmax into Rm ----
        {
            const uint4*  Bl = sB + 3 * (4 * 4 * 32) + lane;
            const float2* bp = (const float2*)(sbias_b + 3 * 64);
            #pragma unroll
            for (int jp = 0; jp < 4; jp++) {
                float2 bva = bp[4 * (2*jp) + t];
                float2 bvb = bp[4 * (2*jp+1) + t];
                float Da0[4] = {bva.x, bva.y, bva.x, bva.y};
                float Da1[4] = {bva.x, bva.y, bva.x, bva.y};
                float Db0[4] = {bvb.x, bvb.y, bvb.x, bvb.y};
                float Db1[4] = {bvb.x, bvb.y, bvb.x, bvb.y};
                #pragma unroll
                for (int sb = 0; sb < 4; sb++) {
                    uint4 bf = Bl[(sb * 4 + jp) * 32];
                    const uint32_t* p0 = A0 + 4 * sb;
                    const uint32_t* p1 = A1 + 4 * sb;
                    MMA16816(Da0, p0[0], p0[1], p0[2], p0[3], bf.x, bf.y);
                    MMA16816(Da1, p1[0], p1[1], p1[2], p1[3], bf.x, bf.y);
                    MMA16816(Db0, p0[0], p0[1], p0[2], p0[3], bf.z, bf.w);
                    MMA16816(Db1, p1[0], p1[1], p1[2], p1[3], bf.z, bf.w);
                }
                Rm0[2*jp]   = fmaxf(Rm0[2*jp],   fmaxf(fmaxf(lrelu(Da0[0]), lrelu(Da0[2])),
                                                       fmaxf(lrelu(Da1[0]), lrelu(Da1[2]))));
                Rm1[2*jp]   = fmaxf(Rm1[2*jp],   fmaxf(fmaxf(lrelu(Da0[1]), lrelu(Da0[3])),
                                                       fmaxf(lrelu(Da1[1]), lrelu(Da1[3]))));
                Rm0[2*jp+1] = fmaxf(Rm0[2*jp+1], fmaxf(fmaxf(lrelu(Db0[0]), lrelu(Db0[2])),
                                                       fmaxf(lrelu(Db1[0]), lrelu(Db1[2]))));
                Rm1[2*jp+1] = fmaxf(Rm1[2*jp+1], fmaxf(fmaxf(lrelu(Db0[1]), lrelu(Db0[3])),
                                                       fmaxf(lrelu(Db1[1]), lrelu(Db1[3]))));
            }
        }
    }

    // ---- once-per-warp reduce + global atomics ----
    #pragma unroll
    for (int j = 0; j < 8; j++) {
        float m0 = Rm0[j], m1 = Rm1[j];
        m0 = fmaxf(m0, __shfl_xor_sync(0xffffffffu, m0, 4));
        m0 = fmaxf(m0, __shfl_xor_sync(0xffffffffu, m0, 8));
        m0 = fmaxf(m0, __shfl_xor_sync(0xffffffffu, m0, 16));
        m1 = fmaxf(m1, __shfl_xor_sync(0xffffffffu, m1, 4));
        m1 = fmaxf(m1, __shfl_xor_sync(0xffffffffu, m1, 8));
        m1 = fmaxf(m1, __shfl_xor_sync(0xffffffffu, m1, 16));
        if (lane < 4) {
            atomicMax(&g_maxkey[b * 64 + 8 * j + 2 * t],     f2ukey(m0));
            atomicMax(&g_maxkey[b * 64 + 8 * j + 2 * t + 1], f2ukey(m1));
        }
    }
    __threadfence();

    // ---- last CTA writes output and restores global state to 0 ----
    __syncthreads();
    __shared__ int slast;
    if (tid == 0) slast = (atomicAdd(&g_done, 1) == GRID - 1) ? 1 : 0;
    __syncthreads();
    if (slast) {
        __threadfence();
        for (int idx = tid; idx < BATCH * 64; idx += TPB) {
            unsigned k = atomicMax(&g_maxkey[idx], 0u);   // atomic read (0 = identity)
            out[idx] = ukey2f(k);
            g_maxkey[idx] = 0u;                            // restore for next replay
        }
        __threadfence();
        if (tid == 0) g_done = 0;                          // restore counter
    }
}

// ---------------------------------------------------------------------------
extern "C" void kernel_launch(void* const* d_in, const int* in_sizes, int n_in,
                              void* d_out, int out_size) {
    const float* feat = (const float*)d_in[0];
    const float* W0   = (const float*)d_in[1];
    const float* W1   = (const float*)d_in[2];
    const float* W2   = (const float*)d_in[3];
    const float* W3   = (const float*)d_in[4];
    float* out = (float*)d_out;

    cudaFuncSetAttribute(mlp_kernel, cudaFuncAttributeMaxDynamicSharedMemorySize, SM_TOTAL);
    mlp_kernel<<<GRID, TPB, SM_TOTAL>>>(feat, W0, W1, W2, W3, out);
}

// round 14
// speedup vs baseline: 3.6029x; 3.6029x over previous
#include <cuda_runtime.h>
#include <cuda_fp16.h>
#include <cstdint>
#include <limits.h>

// ---------------- problem constants ----------------
#define BATCH   8
#define CDIM    64
#define GDIM    65536
#define NLAYER  4
#define SLOPE   0.1f

#define TPB     256
#define CTAS_PER_SM 2
#define GRID    (148 * CTAS_PER_SM)         // 296
#define WARPS_PER_CTA (TPB / 32)
#define NWARPS  (GRID * WARPS_PER_CTA)      // 2368
#define WARPS_PER_BATCH (NWARPS / BATCH)    // 296
#define TILES_PER_BATCH (GDIM / 32)         // 2048 tiles of 32 columns

// smem layout (dynamic)
#define SMB_BYTES   (4 * 4 * 4 * 32 * 16)   // B fragment pairs: 32768
#define SMBIAS_OFF  SMB_BYTES               // 8 x 4 x 64 fp32 = 8192
#define SM_TOTAL    (SMBIAS_OFF + 8192)

#define NEG_INF __int_as_float(0xff800000)

// ---------------- helpers ----------------
__device__ __forceinline__ uint32_t pack_h2(float a, float b) {
    uint32_t p;
    asm("cvt.rn.f16x2.f32 %0, %1, %2;" : "=r"(p) : "f"(b), "f"(a));
    return p;
}

#define MMA16816(d, a0, a1, a2, a3, b0, b1) \
    asm volatile("mma.sync.aligned.m16n8k16.row.col.f32.f16.f16.f32 " \
        "{%0,%1,%2,%3}, {%4,%5,%6,%7}, {%8,%9}, {%0,%1,%2,%3};" \
        : "+f"((d)[0]), "+f"((d)[1]), "+f"((d)[2]), "+f"((d)[3]) \
        : "r"(a0), "r"(a1), "r"(a2), "r"(a3), "r"(b0), "r"(b1))

// monotone uint key; 0 == -inf sentinel (matches zero-init of __device__ globals)
__device__ __forceinline__ unsigned f2ukey(float f) {
    int b = __float_as_int(f);
    b = (b >= 0) ? b : (b ^ 0x7fffffff);
    return (unsigned)b ^ 0x80000000u;
}
__device__ __forceinline__ float ukey2f(unsigned u) {
    int k = (int)(u ^ 0x80000000u);
    return __int_as_float(k >= 0 ? k : (k ^ 0x7fffffff));
}
__device__ __forceinline__ float lrelu(float a) { return fmaxf(a, SLOPE * a); }

// ---------------- device globals (zero-init .bss; mlp restores to 0) --------
__device__ float    g_bias[NLAYER][BATCH][64];
__device__ unsigned g_maxkey[BATCH * 64];
__device__ int      g_done;

// ---------------- kernel 0: bias chain (parallel, one block per batch) ------
__global__ void setup_kernel(const float* __restrict__ feat,
                             const float* __restrict__ W0,
                             const float* __restrict__ W1,
                             const float* __restrict__ W2,
                             const float* __restrict__ W3) {
    const float* Ws[NLAYER] = {W0, W1, W2, W3};
    const int b = blockIdx.x;
    const int o = threadIdx.x;
    __shared__ float sx0[64];
    __shared__ float sy[64];

    sx0[o] = feat[(size_t)b * CDIM * GDIM + (size_t)o * GDIM];  // g = 0
    __syncthreads();
    #pragma unroll 1
    for (int l = 0; l < NLAYER; l++) {
        const float* wr = Ws[l] + o * 128;
        float da = 0.f, db = 0.f;
        #pragma unroll
        for (int c = 0; c < 64; c++) {
            float xv = sx0[c];
            da = fmaf(wr[c], xv, da);
            db = fmaf(wr[64 + c], xv, db);
        }
        g_bias[l][b][o] = -db;
        sy[o] = lrelu(da);
        __syncthreads();
        sx0[o] = sy[o];
        __syncthreads();
    }
}

// ---------------- kernel 1: persistent mma.sync MLP ------------------------
// M=32 tiles, batch-locked warps, register running max, float4 permuted loads.
__global__ void __launch_bounds__(TPB, CTAS_PER_SM)
mlp_kernel(const float* __restrict__ feat,
           const float* __restrict__ W0, const float* __restrict__ W1,
           const float* __restrict__ W2, const float* __restrict__ W3,
           float* __restrict__ out) {
    extern __shared__ char smem[];
    uint4* sB    = (uint4*)smem;                    // [l][sb:4][jp:4][lane:32]
    float* sbias = (float*)(smem + SMBIAS_OFF);     // [b][l][o]

    const int tid  = threadIdx.x;
    const int wid  = tid >> 5;
    const int lane = tid & 31;
    const int g    = lane >> 2;
    const int t    = lane & 3;

    // ---- prologue: pack B fragment PAIRS (Weff -> fp16) + bias copy ----
    {
        const float* Ws[NLAYER] = {W0, W1, W2, W3};
        for (int idx = tid; idx < 4 * 4 * 4 * 32; idx += TPB) {
            int ln = idx & 31, jp = (idx >> 5) & 3, sb = (idx >> 7) & 3, l = idx >> 9;
            int gg = ln >> 2, tt = ln & 3;
            int cb = 16 * sb + 2 * tt;
            uint32_t v[4];
            #pragma unroll
            for (int h = 0; h < 2; h++) {
                int o = 8 * (2 * jp + h) + gg;
                const float* W = Ws[l] + o * 128;
                float v0 = W[cb]     + W[64 + cb];
                float v1 = W[cb + 1] + W[64 + cb + 1];
                float v8 = W[cb + 8] + W[64 + cb + 8];
                float v9 = W[cb + 9] + W[64 + cb + 9];
                v[2 * h]     = pack_h2(v0, v1);
                v[2 * h + 1] = pack_h2(v8, v9);
            }
            sB[idx] = make_uint4(v[0], v[1], v[2], v[3]);
        }
        for (int idx = tid; idx < BATCH * NLAYER * 64; idx += TPB) {
            int b = idx >> 8, l = (idx >> 6) & 3, o = idx & 63;
            sbias[idx] = g_bias[l][b][o];
        }
    }
    __syncthreads();

    // ---- batch-locked warp -> tile mapping ----
    const int wglobal = blockIdx.x * WARPS_PER_CTA + wid;
    const int b       = wglobal & 7;
    const int tstart  = wglobal >> 3;
    const float* fbase = feat + (size_t)b * CDIM * GDIM;
    const float* sbias_b = sbias + b * NLAYER * 64;

    // register running max (this lane's D-rows only; cross-row reduce at end)
    float Rm0[8], Rm1[8];
    #pragma unroll
    for (int j = 0; j < 8; j++) { Rm0[j] = NEG_INF; Rm1[j] = NEG_INF; }

    for (int ti = tstart; ti < TILES_PER_BATCH; ti += WARPS_PER_BATCH) {
        // ---- vectorized X load (column-permuted fragment mapping) ----
        // Columns within the 32-tile are permuted (max over all cols is
        // permutation-invariant): lane (g,t) loads float4 at col 4g.
        uint32_t A0[16], A1[16];
        {
            const float* fp = fbase + ((uint32_t)ti << 5);
            #pragma unroll
            for (int s = 0; s < 4; s++) {
                const uint32_t c0 = 16 * s + 2 * t;
                const float4 v0 = __ldg((const float4*)(fp + (size_t)c0 * GDIM) + g);
                const float4 v1 = __ldg((const float4*)(fp + (size_t)(c0 + 1) * GDIM) + g);
                const float4 v8 = __ldg((const float4*)(fp + (size_t)(c0 + 8) * GDIM) + g);
                const float4 v9 = __ldg((const float4*)(fp + (size_t)(c0 + 9) * GDIM) + g);
                A0[4*s+0] = pack_h2(v0.x, v1.x);
                A0[4*s+1] = pack_h2(v0.y, v1.y);
                A0[4*s+2] = pack_h2(v8.x, v9.x);
                A0[4*s+3] = pack_h2(v8.y, v9.y);
                A1[4*s+0] = pack_h2(v0.z, v1.z);
                A1[4*s+1] = pack_h2(v0.w, v1.w);
                A1[4*s+2] = pack_h2(v8.z, v9.z);
                A1[4*s+3] = pack_h2(v8.w, v9.w);
            }
        }

        // ---- layers 0..2: all-j-live D, in-place A rewrite ----
        #pragma unroll 1
        for (int l = 0; l < NLAYER - 1; l++) {
            float D0[8][4], D1[8][4];
            const float2* bp = (const float2*)(sbias_b + l * 64);
            #pragma unroll
            for (int j = 0; j < 8; j++) {
                float2 bv = bp[4 * j + t];
                D0[j][0] = bv.x; D0[j][1] = bv.y; D0[j][2] = bv.x; D0[j][3] = bv.y;
                D1[j][0] = bv.x; D1[j][1] = bv.y; D1[j][2] = bv.x; D1[j][3] = bv.y;
            }
            const uint4* Bl = sB + l * (4 * 4 * 32) + lane;
            #pragma unroll
            for (int sb = 0; sb < 4; sb++) {
                const uint32_t* p0 = A0 + 4 * sb;
                const uint32_t* p1 = A1 + 4 * sb;
                #pragma unroll
                for (int jp = 0; jp < 4; jp++) {
                    uint4 bf = Bl[(sb * 4 + jp) * 32];
                    MMA16816(D0[2*jp],   p0[0], p0[1], p0[2], p0[3], bf.x, bf.y);
                    MMA16816(D1[2*jp],   p1[0], p1[1], p1[2], p1[3], bf.x, bf.y);
                    MMA16816(D0[2*jp+1], p0[0], p0[1], p0[2], p0[3], bf.z, bf.w);
                    MMA16816(D1[2*jp+1], p1[0], p1[1], p1[2], p1[3], bf.z, bf.w);
                }
            }
            #pragma unroll
            for (int j = 0; j < 8; j++) {
                const int s4 = ((j >> 1) << 2) + ((j & 1) << 1);
                A0[s4 + 0] = pack_h2(lrelu(D0[j][0]), lrelu(D0[j][1]));
                A0[s4 + 1] = pack_h2(lrelu(D0[j][2]), lrelu(D0[j][3]));
                A1[s4 + 0] = pack_h2(lrelu(D1[j][0]), lrelu(D1[j][1]));
                A1[s4 + 1] = pack_h2(lrelu(D1[j][2]), lrelu(D1[j][3]));
            }
        }

        // ---- final layer: j-outer (8 D regs live), fmax into Rm ----
        {
            const uint4*  Bl = sB + 3 * (4 * 4 * 32) + lane;
            const float2* bp = (const float2*)(sbias_b + 3 * 64);
            #pragma unroll
            for (int jp = 0; jp < 4; jp++) {
                float2 bva = bp[4 * (2*jp) + t];
                float2 bvb = bp[4 * (2*jp+1) + t];
                float Da0[4] = {bva.x, bva.y, bva.x, bva.y};
                float Da1[4] = {bva.x, bva.y, bva.x, bva.y};
                float Db0[4] = {bvb.x, bvb.y, bvb.x, bvb.y};
                float Db1[4] = {bvb.x, bvb.y, bvb.x, bvb.y};
                #pragma unroll
                for (int sb = 0; sb < 4; sb++) {
                    uint4 bf = Bl[(sb * 4 + jp) * 32];
                    const uint32_t* p0 = A0 + 4 * sb;
                    const uint32_t* p1 = A1 + 4 * sb;
                    MMA16816(Da0, p0[0], p0[1], p0[2], p0[3], bf.x, bf.y);
                    MMA16816(Da1, p1[0], p1[1], p1[2], p1[3], bf.x, bf.y);
                    MMA16816(Db0, p0[0], p0[1], p0[2], p0[3], bf.z, bf.w);
                    MMA16816(Db1, p1[0], p1[1], p1[2], p1[3], bf.z, bf.w);
                }
                Rm0[2*jp]   = fmaxf(Rm0[2*jp],   fmaxf(fmaxf(lrelu(Da0[0]), lrelu(Da0[2])),
                                                       fmaxf(lrelu(Da1[0]), lrelu(Da1[2]))));
                Rm1[2*jp]   = fmaxf(Rm1[2*jp],   fmaxf(fmaxf(lrelu(Da0[1]), lrelu(Da0[3])),
                                                       fmaxf(lrelu(Da1[1]), lrelu(Da1[3]))));
                Rm0[2*jp+1] = fmaxf(Rm0[2*jp+1], fmaxf(fmaxf(lrelu(Db0[0]), lrelu(Db0[2])),
                                                       fmaxf(lrelu(Db1[0]), lrelu(Db1[2]))));
                Rm1[2*jp+1] = fmaxf(Rm1[2*jp+1], fmaxf(fmaxf(lrelu(Db0[1]), lrelu(Db0[3])),
                                                       fmaxf(lrelu(Db1[1]), lrelu(Db1[3]))));
            }
        }
    }

    // ---- once-per-warp reduce + global atomics ----
    #pragma unroll
    for (int j = 0; j < 8; j++) {
        float m0 = Rm0[j], m1 = Rm1[j];
        m0 = fmaxf(m0, __shfl_xor_sync(0xffffffffu, m0, 4));
        m0 = fmaxf(m0, __shfl_xor_sync(0xffffffffu, m0, 8));
        m0 = fmaxf(m0, __shfl_xor_sync(0xffffffffu, m0, 16));
        m1 = fmaxf(m1, __shfl_xor_sync(0xffffffffu, m1, 4));
        m1 = fmaxf(m1, __shfl_xor_sync(0xffffffffu, m1, 8));
        m1 = fmaxf(m1, __shfl_xor_sync(0xffffffffu, m1, 16));
        if (lane < 4) {
            atomicMax(&g_maxkey[b * 64 + 8 * j + 2 * t],     f2ukey(m0));
            atomicMax(&g_maxkey[b * 64 + 8 * j + 2 * t + 1], f2ukey(m1));
        }
    }
    __threadfence();

    // ---- last CTA writes output and restores global state to 0 ----
    __syncthreads();
    __shared__ int slast;
    if (tid == 0) slast = (atomicAdd(&g_done, 1) == GRID - 1) ? 1 : 0;
    __syncthreads();
    if (slast) {
        __threadfence();
        for (int idx = tid; idx < BATCH * 64; idx += TPB) {
            unsigned k = atomicMax(&g_maxkey[idx], 0u);   // atomic read (0 = identity)
            out[idx] = ukey2f(k);
            g_maxkey[idx] = 0u;                            // restore for next replay
        }
        __threadfence();
        if (tid == 0) g_done = 0;                          // restore counter
    }
}

// ---------------------------------------------------------------------------
extern "C" void kernel_launch(void* const* d_in, const int* in_sizes, int n_in,
                              void* d_out, int out_size) {
    const float* feat = (const float*)d_in[0];
    const float* W0   = (const float*)d_in[1];
    const float* W1   = (const float*)d_in[2];
    const float* W2   = (const float*)d_in[3];
    const float* W3   = (const float*)d_in[4];
    float* out = (float*)d_out;

    cudaFuncSetAttribute(mlp_kernel, cudaFuncAttributeMaxDynamicSharedMemorySize, SM_TOTAL);

    setup_kernel<<<BATCH, 64>>>(feat, W0, W1, W2, W3);               // 0
    mlp_kernel<<<GRID, TPB, SM_TOTAL>>>(feat, W0, W1, W2, W3, out);  // 1
}